// round 3
// baseline (speedup 1.0000x reference)
#include <cuda_runtime.h>
#include <math.h>

#define NROWS 65536
#define DIM   256
#define KCB   1024

#define OFF_LOSS 0
#define OFF_Q    1
#define OFF_PERP (1 + NROWS*DIM)
#define OFF_EMB  (OFF_PERP + 1)
#define OFF_CS   (OFF_EMB + KCB*DIM)
#define OFF_EMA  (OFF_CS + KCB)

__device__ float  g_A[NROWS];
__device__ float  g_C[KCB];
__device__ int    g_idx[NROWS];
__device__ float  g_counts[KCB];
__device__ float  g_dw[KCB*DIM];
__device__ float  g_cs[KCB];
__device__ double g_lp[2048];

// ---- row squared norms, fp64-accumulated, correctly rounded to fp32 ----
__global__ __launch_bounds__(256) void k_rownorm(const float* __restrict__ src,
                                                 int nrows, int which) {
    int wd = threadIdx.x >> 5, l = threadIdx.x & 31;
    int row = blockIdx.x * 8 + wd;
    if (row >= nrows) return;
    const float4* r4 = (const float4*)(src + (size_t)row * DIM);
    float4 a = r4[l], b = r4[l + 32];
    double s = (double)a.x*a.x + (double)a.y*a.y + (double)a.z*a.z + (double)a.w*a.w
             + (double)b.x*b.x + (double)b.y*b.y + (double)b.z*b.z + (double)b.w*b.w;
#pragma unroll
    for (int o = 16; o; o >>= 1) s += __shfl_down_sync(0xffffffffu, s, o);
    if (!l) { if (which) g_C[row] = (float)s; else g_A[row] = (float)s; }
}

// ---- fused distance GEMM + argmin ----
#define TM 128
#define TN 128
#define TK 32
__global__ __launch_bounds__(256,2) void k_argmin(const float* __restrict__ x,
                                                  const float* __restrict__ w) {
    __shared__ float xs[TK][TM+4];
    __shared__ float ws[TK][TN+4];
    __shared__ float sC[KCB];
    int tid = threadIdx.x, tx = tid & 15, ty = tid >> 4;
    int rowBase = blockIdx.x * TM;
    for (int i = tid; i < KCB; i += 256) sC[i] = g_C[i];
    float Areg[8];
#pragma unroll
    for (int i = 0; i < 8; i++) Areg[i] = g_A[rowBase + ty*8 + i];
    float bD[8]; int bI[8];
#pragma unroll
    for (int i = 0; i < 8; i++) { bD[i] = 3.4e38f; bI[i] = 0; }

    for (int ct = 0; ct < KCB; ct += TN) {
        float acc[8][8];
#pragma unroll
        for (int i = 0; i < 8; i++)
#pragma unroll
            for (int j = 0; j < 8; j++) acc[i][j] = 0.f;
        for (int kc = 0; kc < DIM; kc += TK) {
            __syncthreads();
#pragma unroll
            for (int l = 0; l < 4; l++) {
                int lin = l*256 + tid, r = lin >> 3, c = lin & 7;
                float4 v = *(const float4*)(x + (size_t)(rowBase + r)*DIM + kc + c*4);
                xs[c*4+0][r] = v.x; xs[c*4+1][r] = v.y;
                xs[c*4+2][r] = v.z; xs[c*4+3][r] = v.w;
                float4 u = *(const float4*)(w + (size_t)(ct + r)*DIM + kc + c*4);
                ws[c*4+0][r] = u.x; ws[c*4+1][r] = u.y;
                ws[c*4+2][r] = u.z; ws[c*4+3][r] = u.w;
            }
            __syncthreads();
#pragma unroll
            for (int kk = 0; kk < TK; kk++) {
                float a[8], b[8];
#pragma unroll
                for (int i = 0; i < 8; i++) a[i] = xs[kk][ty*8 + i];
#pragma unroll
                for (int j = 0; j < 8; j++) b[j] = ws[kk][tx*8 + j];
#pragma unroll
                for (int i = 0; i < 8; i++)
#pragma unroll
                    for (int j = 0; j < 8; j++) acc[i][j] += a[i] * b[j];
            }
        }
#pragma unroll
        for (int j = 0; j < 8; j++) {
            int code = ct + tx*8 + j;
            float Cj = sC[code];
#pragma unroll
            for (int i = 0; i < 8; i++) {
                float d = __fadd_rn(__fsub_rn(Areg[i], __fmul_rn(2.0f, acc[i][j])), Cj);
                if (d < bD[i] || (d == bD[i] && code < bI[i])) { bD[i] = d; bI[i] = code; }
            }
        }
    }
    __syncthreads();
    float* rD = &xs[0][0]; int* rI = (int*)&ws[0][0];
#pragma unroll
    for (int i = 0; i < 8; i++) { int r = ty*8 + i; rD[r*16 + tx] = bD[i]; rI[r*16 + tx] = bI[i]; }
    __syncthreads();
    if (tid < TM) {
        float bd = rD[tid*16]; int bi = rI[tid*16];
#pragma unroll
        for (int t = 1; t < 16; t++) {
            float d = rD[tid*16 + t]; int c = rI[tid*16 + t];
            if (d < bd || (d == bd && c < bi)) { bd = d; bi = c; }
        }
        g_idx[rowBase + tid] = bi;
    }
}

// ---- gather codebook, write straight-through output, loss partials ----
__global__ __launch_bounds__(256) void k_quant(const float* __restrict__ x,
                                               const float* __restrict__ w,
                                               float* __restrict__ out) {
    __shared__ double sr[256];
    double ls = 0.0;
    int stride = gridDim.x * 256;
    for (int e4 = blockIdx.x*256 + threadIdx.x; e4 < NROWS*DIM/4; e4 += stride) {
        int row = e4 >> 6, c4 = e4 & 63;
        int k = g_idx[row];
        float4 xv = ((const float4*)x)[e4];
        float4 qv = ((const float4*)w)[k*64 + c4];
        float d0 = __fsub_rn(qv.x, xv.x), d1 = __fsub_rn(qv.y, xv.y);
        float d2 = __fsub_rn(qv.z, xv.z), d3 = __fsub_rn(qv.w, xv.w);
        float* o = out + OFF_Q + (size_t)e4*4;
        o[0] = __fadd_rn(xv.x, d0); o[1] = __fadd_rn(xv.y, d1);
        o[2] = __fadd_rn(xv.z, d2); o[3] = __fadd_rn(xv.w, d3);
        ls += (double)d0*d0 + (double)d1*d1 + (double)d2*d2 + (double)d3*d3;
    }
    sr[threadIdx.x] = ls;
    __syncthreads();
    for (int o = 128; o; o >>= 1) { if (threadIdx.x < o) sr[threadIdx.x] += sr[threadIdx.x + o]; __syncthreads(); }
    if (!threadIdx.x) g_lp[blockIdx.x] = sr[0];
}

// ---- deterministic per-code counts + dw (one block per code) ----
__global__ __launch_bounds__(256) void k_counts(const float* __restrict__ x) {
    __shared__ int list[4096];
    __shared__ int cnt;
    int k = blockIdx.x, d = threadIdx.x;
    float acc = 0.f; int total = 0;
    for (int base = 0; base < NROWS; base += 4096) {
        if (!threadIdx.x) cnt = 0;
        __syncthreads();
        for (int i = threadIdx.x; i < 4096; i += 256)
            if (g_idx[base + i] == k) list[atomicAdd(&cnt, 1)] = base + i;
        __syncthreads();
        int m = cnt;
        for (int j = 0; j < m; j++) acc += x[(size_t)list[j]*DIM + d];
        total += m;
        __syncthreads();
    }
    g_dw[k*DIM + d] = acc;
    if (!threadIdx.x) g_counts[k] = (float)total;
}

// ---- scalars: loss, new_cluster_size, cs, perplexity ----
__global__ __launch_bounds__(256) void k_scalars(const float* __restrict__ ecs,
                                                 float* __restrict__ out) {
    __shared__ double sd[256];
    int t = threadIdx.x;
    double s = 0;
    for (int i = t; i < 2048; i += 256) s += g_lp[i];
    sd[t] = s; __syncthreads();
    for (int o = 128; o; o >>= 1) { if (t < o) sd[t] += sd[t + o]; __syncthreads(); }
    double loss = 0.25 * sd[0] / ((double)NROWS * DIM);

    double ns = 0;
    for (int k = t; k < KCB; k += 256) {
        float ncs = __fadd_rn(__fmul_rn(0.99f, ecs[k]), __fmul_rn(0.01f, g_counts[k]));
        out[OFF_CS + k] = ncs;
        ns += ncs;
    }
    __syncthreads(); sd[t] = ns; __syncthreads();
    for (int o = 128; o; o >>= 1) { if (t < o) sd[t] += sd[t + o]; __syncthreads(); }
    float nf = (float)sd[0];
    float denom = __fadd_rn(nf, (float)(1024.0 * 1e-5));
    for (int k = t; k < KCB; k += 256) {
        float ncs = out[OFF_CS + k];
        g_cs[k] = __fmul_rn(__fdiv_rn(__fadd_rn(ncs, 1e-5f), denom), nf);
    }
    double ps = 0;
    for (int k = t; k < KCB; k += 256) {
        double p = (double)g_counts[k] / (double)NROWS;
        ps += p * log(p + 1e-10);
    }
    __syncthreads(); sd[t] = ps; __syncthreads();
    for (int o = 128; o; o >>= 1) { if (t < o) sd[t] += sd[t + o]; __syncthreads(); }
    if (!t) { out[OFF_LOSS] = (float)loss; out[OFF_PERP] = (float)exp(-sd[0]); }
}

// ---- EMA codebook update ----
__global__ __launch_bounds__(256) void k_emb(const float* __restrict__ emaw,
                                             float* __restrict__ out) {
    int e = blockIdx.x*256 + threadIdx.x;
    if (e >= KCB*DIM) return;
    int k = e >> 8;
    float ne = __fadd_rn(__fmul_rn(0.99f, emaw[e]), __fmul_rn(0.01f, g_dw[e]));
    out[OFF_EMA + e] = ne;
    out[OFF_EMB + e] = __fdiv_rn(ne, g_cs[k]);
}

extern "C" void kernel_launch(void* const* d_in, const int* in_sizes, int n_in,
                              void* d_out, int out_size) {
    const float* x    = (const float*)d_in[0];
    const float* w    = (const float*)d_in[1];
    const float* ecs  = (const float*)d_in[2];
    const float* emaw = (const float*)d_in[3];
    float* out = (float*)d_out;

    k_rownorm<<<NROWS/8, 256>>>(x, NROWS, 0);
    k_rownorm<<<KCB/8,   256>>>(w, KCB,   1);
    k_argmin<<<NROWS/TM, 256>>>(x, w);
    k_quant<<<2048, 256>>>(x, w, out);
    k_counts<<<KCB, 256>>>(x);
    k_scalars<<<1, 256>>>(ecs, out);
    k_emb<<<KCB*DIM/256, 256>>>(emaw, out);
}

// round 4
// speedup vs baseline: 1.1170x; 1.1170x over previous
#include <cuda_runtime.h>
#include <math.h>

#define NROWS 65536
#define DIM   256
#define KCB   1024

#define OFF_LOSS 0
#define OFF_Q    1
#define OFF_PERP (1 + NROWS*DIM)
#define OFF_EMB  (OFF_PERP + 1)
#define OFF_CS   (OFF_EMB + KCB*DIM)
#define OFF_EMA  (OFF_CS + KCB)

__device__ float  g_A[NROWS];
__device__ float  g_C[KCB];
__device__ int    g_idx[NROWS];
__device__ float  g_counts[KCB];
__device__ float  g_dw[KCB*DIM];
__device__ float  g_cs[KCB];
__device__ double g_lp[2048];

// ---- row squared norms, fp64-accumulated, correctly rounded to fp32 ----
__global__ __launch_bounds__(256) void k_rownorm(const float* __restrict__ src,
                                                 int nrows, int which) {
    int wd = threadIdx.x >> 5, l = threadIdx.x & 31;
    int row = blockIdx.x * 8 + wd;
    if (row >= nrows) return;
    const float4* r4 = (const float4*)(src + (size_t)row * DIM);
    float4 a = r4[l], b = r4[l + 32];
    double s = (double)a.x*a.x + (double)a.y*a.y + (double)a.z*a.z + (double)a.w*a.w
             + (double)b.x*b.x + (double)b.y*b.y + (double)b.z*b.z + (double)b.w*b.w;
#pragma unroll
    for (int o = 16; o; o >>= 1) s += __shfl_down_sync(0xffffffffu, s, o);
    if (!l) { if (which) g_C[row] = (float)s; else g_A[row] = (float)s; }
}

// ---- fused distance GEMM + argmin (FFMA2 packed inner loop) ----
#define TM 128
#define TN 128
#define TK 32
__global__ __launch_bounds__(256,2) void k_argmin(const float* __restrict__ x,
                                                  const float* __restrict__ w) {
    __shared__ float xs[TK][TM+4];
    __shared__ float ws[TK][TN+4];
    __shared__ float sC[KCB];
    int tid = threadIdx.x, tx = tid & 15, ty = tid >> 4;
    int rowBase = blockIdx.x * TM;
    for (int i = tid; i < KCB; i += 256) sC[i] = g_C[i];
    float Areg[8];
#pragma unroll
    for (int i = 0; i < 8; i++) Areg[i] = g_A[rowBase + ty*8 + i];
    float bD[8]; int bI[8];
#pragma unroll
    for (int i = 0; i < 8; i++) { bD[i] = 3.4e38f; bI[i] = 0; }

    for (int ct = 0; ct < KCB; ct += TN) {
        // packed accumulators: accp[i][j] holds columns (2j, 2j+1) for row i
        unsigned long long accp[8][4];
#pragma unroll
        for (int i = 0; i < 8; i++)
#pragma unroll
            for (int j = 0; j < 4; j++) accp[i][j] = 0ull;

        for (int kc = 0; kc < DIM; kc += TK) {
            __syncthreads();
#pragma unroll
            for (int l = 0; l < 4; l++) {
                int lin = l*256 + tid, r = lin >> 3, c = lin & 7;
                float4 v = *(const float4*)(x + (size_t)(rowBase + r)*DIM + kc + c*4);
                xs[c*4+0][r] = v.x; xs[c*4+1][r] = v.y;
                xs[c*4+2][r] = v.z; xs[c*4+3][r] = v.w;
                float4 u = *(const float4*)(w + (size_t)(ct + r)*DIM + kc + c*4);
                ws[c*4+0][r] = u.x; ws[c*4+1][r] = u.y;
                ws[c*4+2][r] = u.z; ws[c*4+3][r] = u.w;
            }
            __syncthreads();
#pragma unroll 8
            for (int kk = 0; kk < TK; kk++) {
                float a[8];
                *(float4*)(a)     = *(const float4*)&xs[kk][ty*8];
                *(float4*)(a + 4) = *(const float4*)&xs[kk][ty*8 + 4];
                unsigned long long ap[8];
#pragma unroll
                for (int i = 0; i < 8; i++) {
                    unsigned int ai = __float_as_uint(a[i]);
                    asm("mov.b64 %0, {%1, %1};" : "=l"(ap[i]) : "r"(ai));
                }
                unsigned long long bp[4];
#pragma unroll
                for (int j = 0; j < 4; j++)
                    bp[j] = *(const unsigned long long*)&ws[kk][tx*8 + 2*j];
#pragma unroll
                for (int i = 0; i < 8; i++)
#pragma unroll
                    for (int j = 0; j < 4; j++)
                        asm("fma.rn.f32x2 %0, %1, %2, %0;"
                            : "+l"(accp[i][j]) : "l"(ap[i]), "l"(bp[j]));
            }
        }
        // unpack + distances with EXACT reference rounding chain
#pragma unroll
        for (int j = 0; j < 4; j++) {
            int c0 = ct + tx*8 + 2*j;
            float C0 = sC[c0], C1 = sC[c0 + 1];
#pragma unroll
            for (int i = 0; i < 8; i++) {
                float lo, hi;
                asm("mov.b64 {%0, %1}, %2;" : "=f"(lo), "=f"(hi) : "l"(accp[i][j]));
                float d0 = __fadd_rn(__fsub_rn(Areg[i], __fmul_rn(2.0f, lo)), C0);
                float d1 = __fadd_rn(__fsub_rn(Areg[i], __fmul_rn(2.0f, hi)), C1);
                if (d0 < bD[i] || (d0 == bD[i] && c0 < bI[i])) { bD[i] = d0; bI[i] = c0; }
                if (d1 < bD[i] || (d1 == bD[i] && c0+1 < bI[i])) { bD[i] = d1; bI[i] = c0+1; }
            }
        }
    }
    __syncthreads();
    float* rD = &xs[0][0]; int* rI = (int*)&ws[0][0];
#pragma unroll
    for (int i = 0; i < 8; i++) { int r = ty*8 + i; rD[r*16 + tx] = bD[i]; rI[r*16 + tx] = bI[i]; }
    __syncthreads();
    if (tid < TM) {
        float bd = rD[tid*16]; int bi = rI[tid*16];
#pragma unroll
        for (int t = 1; t < 16; t++) {
            float d = rD[tid*16 + t]; int c = rI[tid*16 + t];
            if (d < bd || (d == bd && c < bi)) { bd = d; bi = c; }
        }
        g_idx[rowBase + tid] = bi;
    }
}

// ---- gather codebook, write straight-through output, loss partials ----
__global__ __launch_bounds__(256) void k_quant(const float* __restrict__ x,
                                               const float* __restrict__ w,
                                               float* __restrict__ out) {
    __shared__ double sr[256];
    double ls = 0.0;
    int stride = gridDim.x * 256;
    for (int e4 = blockIdx.x*256 + threadIdx.x; e4 < NROWS*DIM/4; e4 += stride) {
        int row = e4 >> 6, c4 = e4 & 63;
        int k = g_idx[row];
        float4 xv = ((const float4*)x)[e4];
        float4 qv = ((const float4*)w)[k*64 + c4];
        float d0 = __fsub_rn(qv.x, xv.x), d1 = __fsub_rn(qv.y, xv.y);
        float d2 = __fsub_rn(qv.z, xv.z), d3 = __fsub_rn(qv.w, xv.w);
        float* o = out + OFF_Q + (size_t)e4*4;
        o[0] = __fadd_rn(xv.x, d0); o[1] = __fadd_rn(xv.y, d1);
        o[2] = __fadd_rn(xv.z, d2); o[3] = __fadd_rn(xv.w, d3);
        float s4 = __fmaf_rn(d0, d0, __fmaf_rn(d1, d1, __fmaf_rn(d2, d2, d3*d3)));
        ls += (double)s4;
    }
    sr[threadIdx.x] = ls;
    __syncthreads();
    for (int o = 128; o; o >>= 1) { if (threadIdx.x < o) sr[threadIdx.x] += sr[threadIdx.x + o]; __syncthreads(); }
    if (!threadIdx.x) g_lp[blockIdx.x] = sr[0];
}

// ---- deterministic per-code counts + dw (one block per code) ----
__global__ __launch_bounds__(256) void k_counts(const float* __restrict__ x) {
    __shared__ int list[4096];
    __shared__ int cnt;
    int k = blockIdx.x, d = threadIdx.x;
    float acc = 0.f; int total = 0;
    for (int base = 0; base < NROWS; base += 4096) {
        if (!threadIdx.x) cnt = 0;
        __syncthreads();
        for (int i = threadIdx.x; i < 4096; i += 256)
            if (g_idx[base + i] == k) list[atomicAdd(&cnt, 1)] = base + i;
        __syncthreads();
        int m = cnt;
        for (int j = 0; j < m; j++) acc += x[(size_t)list[j]*DIM + d];
        total += m;
        __syncthreads();
    }
    g_dw[k*DIM + d] = acc;
    if (!threadIdx.x) g_counts[k] = (float)total;
}

// ---- scalars: loss, new_cluster_size, cs, perplexity ----
__global__ __launch_bounds__(256) void k_scalars(const float* __restrict__ ecs,
                                                 float* __restrict__ out) {
    __shared__ double sd[256];
    int t = threadIdx.x;
    double s = 0;
    for (int i = t; i < 2048; i += 256) s += g_lp[i];
    sd[t] = s; __syncthreads();
    for (int o = 128; o; o >>= 1) { if (t < o) sd[t] += sd[t + o]; __syncthreads(); }
    double loss = 0.25 * sd[0] / ((double)NROWS * DIM);

    double ns = 0;
    for (int k = t; k < KCB; k += 256) {
        float ncs = __fadd_rn(__fmul_rn(0.99f, ecs[k]), __fmul_rn(0.01f, g_counts[k]));
        out[OFF_CS + k] = ncs;
        ns += ncs;
    }
    __syncthreads(); sd[t] = ns; __syncthreads();
    for (int o = 128; o; o >>= 1) { if (t < o) sd[t] += sd[t + o]; __syncthreads(); }
    float nf = (float)sd[0];
    float denom = __fadd_rn(nf, (float)(1024.0 * 1e-5));
    for (int k = t; k < KCB; k += 256) {
        float ncs = out[OFF_CS + k];
        g_cs[k] = __fmul_rn(__fdiv_rn(__fadd_rn(ncs, 1e-5f), denom), nf);
    }
    double ps = 0;
    for (int k = t; k < KCB; k += 256) {
        double p = (double)g_counts[k] / (double)NROWS;
        ps += p * log(p + 1e-10);
    }
    __syncthreads(); sd[t] = ps; __syncthreads();
    for (int o = 128; o; o >>= 1) { if (t < o) sd[t] += sd[t + o]; __syncthreads(); }
    if (!t) { out[OFF_LOSS] = (float)loss; out[OFF_PERP] = (float)exp(-sd[0]); }
}

// ---- EMA codebook update ----
__global__ __launch_bounds__(256) void k_emb(const float* __restrict__ emaw,
                                             float* __restrict__ out) {
    int e = blockIdx.x*256 + threadIdx.x;
    if (e >= KCB*DIM) return;
    int k = e >> 8;
    float ne = __fadd_rn(__fmul_rn(0.99f, emaw[e]), __fmul_rn(0.01f, g_dw[e]));
    out[OFF_EMA + e] = ne;
    out[OFF_EMB + e] = __fdiv_rn(ne, g_cs[k]);
}

extern "C" void kernel_launch(void* const* d_in, const int* in_sizes, int n_in,
                              void* d_out, int out_size) {
    const float* x    = (const float*)d_in[0];
    const float* w    = (const float*)d_in[1];
    const float* ecs  = (const float*)d_in[2];
    const float* emaw = (const float*)d_in[3];
    float* out = (float*)d_out;

    k_rownorm<<<NROWS/8, 256>>>(x, NROWS, 0);
    k_rownorm<<<KCB/8,   256>>>(w, KCB,   1);
    k_argmin<<<NROWS/TM, 256>>>(x, w);
    k_quant<<<2048, 256>>>(x, w, out);
    k_counts<<<KCB, 256>>>(x);
    k_scalars<<<1, 256>>>(ecs, out);
    k_emb<<<KCB*DIM/256, 256>>>(emaw, out);
}

// round 8
// speedup vs baseline: 1.1680x; 1.0457x over previous
#include <cuda_runtime.h>
#include <cuda_bf16.h>
#include <mma.h>
#include <math.h>

using namespace nvcuda;

#define NROWS 65536
#define DIM   256
#define KCB   1024

#define OFF_LOSS 0
#define OFF_Q    1
#define OFF_PERP (1 + NROWS*DIM)
#define OFF_EMB  (OFF_PERP + 1)
#define OFF_CS   (OFF_EMB + KCB*DIM)
#define OFF_EMA  (OFF_CS + KCB)

__device__ float  g_A[NROWS];
__device__ float  g_C[KCB];
__device__ int    g_idx[NROWS];
__device__ int    g_cand[NROWS*6];
__device__ float  g_counts[KCB];
__device__ float  g_dw[KCB*DIM];
__device__ float  g_cs[KCB];
__device__ double g_lp[2048];

__device__ __align__(16) __nv_bfloat16 g_xs0[NROWS*DIM];
__device__ __align__(16) __nv_bfloat16 g_xs1[NROWS*DIM];
__device__ __align__(16) __nv_bfloat16 g_ws0[KCB*DIM];
__device__ __align__(16) __nv_bfloat16 g_ws1[KCB*DIM];

__device__ __forceinline__ unsigned smem_u32(const void* p) {
    unsigned a;
    asm("{ .reg .u64 t; cvta.to.shared.u64 t, %1; cvt.u32.u64 %0, t; }" : "=r"(a) : "l"(p));
    return a;
}
__device__ __forceinline__ int dless(float da, int ia, float db, int ib) {
    return (da < db) || (da == db && ia < ib);
}
#define CP_ASYNC16(dst, src) asm volatile("cp.async.cg.shared.global [%0], [%1], 16;" :: "r"(dst), "l"(src) : "memory")
#define CP_COMMIT()          asm volatile("cp.async.commit_group;" ::: "memory")
#define CP_WAIT(n)           asm volatile("cp.async.wait_group %0;" :: "n"(n) : "memory")

// ---------------- 2-way bf16 split ----------------
__global__ __launch_bounds__(256) void k_split(const float* __restrict__ s, int n4,
                                               __nv_bfloat16* __restrict__ d0,
                                               __nv_bfloat16* __restrict__ d1) {
    int i = blockIdx.x * 256 + threadIdx.x;
    if (i >= n4) return;
    float4 v = ((const float4*)s)[i];
    ushort4 o0, o1;
#define SPL(c, a, b) { __nv_bfloat16 b0 = __float2bfloat16_rn(c); \
    float f1 = __fsub_rn(c, __bfloat162float(b0)); __nv_bfloat16 b1 = __float2bfloat16_rn(f1); \
    a = __bfloat16_as_ushort(b0); b = __bfloat16_as_ushort(b1); }
    SPL(v.x, o0.x, o1.x); SPL(v.y, o0.y, o1.y);
    SPL(v.z, o0.z, o1.z); SPL(v.w, o0.w, o1.w);
#undef SPL
    ((ushort4*)d0)[i] = o0; ((ushort4*)d1)[i] = o1;
}

// ---- row squared norms (fp64-accumulated) ----
__global__ __launch_bounds__(256) void k_rownorm(const float* __restrict__ src,
                                                 int nrows, int which) {
    int wd = threadIdx.x >> 5, l = threadIdx.x & 31;
    int row = blockIdx.x * 8 + wd;
    if (row >= nrows) return;
    const float4* r4 = (const float4*)(src + (size_t)row * DIM);
    float4 a = r4[l], b = r4[l + 32];
    double s = (double)a.x*a.x + (double)a.y*a.y + (double)a.z*a.z + (double)a.w*a.w
             + (double)b.x*b.x + (double)b.y*b.y + (double)b.z*b.z + (double)b.w*b.w;
#pragma unroll
    for (int o = 16; o; o >>= 1) s += __shfl_down_sync(0xffffffffu, s, o);
    if (!l) { if (which) g_C[row] = (float)s; else g_A[row] = (float)s; }
}

// ---------------- wmma distance GEMM -> top-3 candidates per half ----------------
#define LDA 520
#define LDB 40
#define AS_BYTES (128*LDA*2)
#define BS_BYTES (128*LDB*2)
#define OFF_AS   0
#define OFF_BS   (AS_BYTES)
#define OFF_SC   (OFF_BS + 2*BS_BYTES)
#define OFF_SCR  (OFF_SC + 4096)
#define SMEM_TOT (OFF_SCR + 8192)

__device__ __forceinline__ void prefetch_b(char* smem, int tid, int buf, int kc, int ct) {
    const __nv_bfloat16* wsrc = (kc < 8) ? g_ws0 : (kc < 16 ? g_ws1 : g_ws0);
    int kb = (kc < 8 ? kc : kc < 16 ? kc - 8 : kc - 16) * 32;
    int code = tid >> 1, half = tid & 1;
    const __nv_bfloat16* src = wsrc + (size_t)(ct + code) * DIM + kb + half * 16;
    unsigned dst = smem_u32(smem + OFF_BS + buf * BS_BYTES + (code * LDB + half * 16) * 2);
    CP_ASYNC16(dst, src);
    CP_ASYNC16(dst + 16, src + 8);
    CP_COMMIT();
}

__global__ __launch_bounds__(256) void k_mma_cand() {
    extern __shared__ char smem[];
    __nv_bfloat16* As = (__nv_bfloat16*)(smem + OFF_AS);
    float* sC = (float*)(smem + OFF_SC);
    int tid = threadIdx.x, w = tid >> 5, lane = tid & 31;
    int rowBase = blockIdx.x * 128;
    int rw = w >> 1, cw = w & 1;

    for (int i = tid; i < KCB; i += 256) sC[i] = g_C[i];

    // A resident: s0 cols [0,256), s1 [256,512)
    for (int u = tid; u < 128 * 64; u += 256) {
        int r = u >> 6, c8 = u & 63;
        const __nv_bfloat16* src = (c8 < 32)
            ? (g_xs0 + (size_t)(rowBase + r) * DIM + c8 * 8)
            : (g_xs1 + (size_t)(rowBase + r) * DIM + (c8 - 32) * 8);
        *(uint4*)(As + r * LDA + c8 * 8) = *(const uint4*)src;
    }
    __syncthreads();

    int r_local = lane >> 1;
    int csub = (lane & 1) * 8;
    float Ar[2];
    Ar[0] = g_A[rowBase + rw * 32 + r_local];
    Ar[1] = g_A[rowBase + rw * 32 + 16 + r_local];
    float tD[2][3]; int tI[2][3];
#pragma unroll
    for (int fr = 0; fr < 2; fr++)
#pragma unroll
        for (int s = 0; s < 3; s++) { tD[fr][s] = 3.4e38f; tI[fr][s] = 0x7ffffff0 + s; }

    for (int ct8 = 0; ct8 < 8; ct8++) {
        int ct = ct8 * 128;
        wmma::fragment<wmma::accumulator, 16, 16, 16, float> acc[2][4];
#pragma unroll
        for (int fr = 0; fr < 2; fr++)
#pragma unroll
            for (int fc = 0; fc < 4; fc++) wmma::fill_fragment(acc[fr][fc], 0.0f);

        prefetch_b(smem, tid, 0, 0, ct);
        for (int kc = 0; kc < 24; kc++) {
            if (kc + 1 < 24) { prefetch_b(smem, tid, (kc + 1) & 1, kc + 1, ct); CP_WAIT(1); }
            else             { CP_WAIT(0); }
            __syncthreads();
            const __nv_bfloat16* Bs = (const __nv_bfloat16*)(smem + OFF_BS + (kc & 1) * BS_BYTES);
            int acol = (kc < 8 ? kc * 32 : kc < 16 ? (kc - 8) * 32 : 256 + (kc - 16) * 32);
#pragma unroll
            for (int ks = 0; ks < 2; ks++) {
                wmma::fragment<wmma::matrix_a, 16, 16, 16, __nv_bfloat16, wmma::row_major> af[2];
                wmma::fragment<wmma::matrix_b, 16, 16, 16, __nv_bfloat16, wmma::col_major> bf[4];
#pragma unroll
                for (int fr = 0; fr < 2; fr++)
                    wmma::load_matrix_sync(af[fr], As + (rw * 32 + fr * 16) * LDA + acol + ks * 16, LDA);
#pragma unroll
                for (int fc = 0; fc < 4; fc++)
                    wmma::load_matrix_sync(bf[fc], Bs + (cw * 64 + fc * 16) * LDB + ks * 16, LDB);
#pragma unroll
                for (int fr = 0; fr < 2; fr++)
#pragma unroll
                    for (int fc = 0; fc < 4; fc++)
                        wmma::mma_sync(acc[fr][fc], af[fr], bf[fc], acc[fr][fc]);
            }
            __syncthreads();
        }

        // epilogue: near-exact distances -> per-thread top-3
        float* scr = (float*)(smem + OFF_SCR + w * 1024);
#pragma unroll
        for (int fr = 0; fr < 2; fr++)
#pragma unroll
            for (int fc = 0; fc < 4; fc++) {
                wmma::store_matrix_sync(scr, acc[fr][fc], 16, wmma::mem_row_major);
                __syncwarp();
                int cbase = ct + cw * 64 + fc * 16 + csub;
#pragma unroll
                for (int j = 0; j < 8; j++) {
                    float dot = scr[r_local * 16 + csub + j];
                    int code = cbase + j;
                    float d = __fadd_rn(__fsub_rn(Ar[fr], __fmul_rn(2.0f, dot)), sC[code]);
                    if (dless(d, code, tD[fr][0], tI[fr][0])) {
                        tD[fr][2] = tD[fr][1]; tI[fr][2] = tI[fr][1];
                        tD[fr][1] = tD[fr][0]; tI[fr][1] = tI[fr][0];
                        tD[fr][0] = d; tI[fr][0] = code;
                    } else if (dless(d, code, tD[fr][1], tI[fr][1])) {
                        tD[fr][2] = tD[fr][1]; tI[fr][2] = tI[fr][1];
                        tD[fr][1] = d; tI[fr][1] = code;
                    } else if (dless(d, code, tD[fr][2], tI[fr][2])) {
                        tD[fr][2] = d; tI[fr][2] = code;
                    }
                }
                __syncwarp();
            }
    }

    // merge lane pair (csub 0 & 8) -> top-3 per (row, half); write 3 candidate indices
#pragma unroll
    for (int fr = 0; fr < 2; fr++) {
        float md[6]; int mi[6];
#pragma unroll
        for (int s = 0; s < 3; s++) {
            md[s] = tD[fr][s]; mi[s] = tI[fr][s];
            md[3 + s] = __shfl_xor_sync(0xffffffffu, tD[fr][s], 1);
            mi[3 + s] = __shfl_xor_sync(0xffffffffu, tI[fr][s], 1);
        }
#pragma unroll
        for (int p = 0; p < 3; p++)
#pragma unroll
            for (int q = p + 1; q < 6; q++)
                if (dless(md[q], mi[q], md[p], mi[p])) {
                    float td = md[p]; md[p] = md[q]; md[q] = td;
                    int   ti = mi[p]; mi[p] = mi[q]; mi[q] = ti;
                }
        if ((lane & 1) == 0) {
            int row = rowBase + rw * 32 + fr * 16 + r_local;
#pragma unroll
            for (int s = 0; s < 3; s++) g_cand[row * 6 + cw * 3 + s] = mi[s];
        }
    }
}

// ---------------- exact rescore (replicates R3 SIMT arithmetic) ----------------
__global__ __launch_bounds__(256) void k_rescore(const float* __restrict__ x,
                                                 const float* __restrict__ w) {
    int row = blockIdx.x * 256 + threadIdx.x;
    if (row >= NROWS) return;
    int c[6];
#pragma unroll
    for (int s = 0; s < 6; s++) c[s] = g_cand[row * 6 + s];
    const float4* xr = (const float4*)(x + (size_t)row * DIM);
    const float4* wr[6];
#pragma unroll
    for (int s = 0; s < 6; s++) wr[s] = (const float4*)(w + (size_t)c[s] * DIM);
    float dot[6] = {0.f, 0.f, 0.f, 0.f, 0.f, 0.f};
#pragma unroll 4
    for (int k4 = 0; k4 < 64; k4++) {
        float4 xv = xr[k4];
#pragma unroll
        for (int s = 0; s < 6; s++) {
            float4 wv = wr[s][k4];
            dot[s] = __fmaf_rn(xv.x, wv.x, dot[s]);
            dot[s] = __fmaf_rn(xv.y, wv.y, dot[s]);
            dot[s] = __fmaf_rn(xv.z, wv.z, dot[s]);
            dot[s] = __fmaf_rn(xv.w, wv.w, dot[s]);
        }
    }
    float A = g_A[row];
    float bd = 3.4e38f; int bi = 0x7fffffff;
#pragma unroll
    for (int s = 0; s < 6; s++) {
        float d = __fadd_rn(__fsub_rn(A, __fmul_rn(2.0f, dot[s])), g_C[c[s]]);
        if (dless(d, c[s], bd, bi)) { bd = d; bi = c[s]; }
    }
    g_idx[row] = bi;
}

// ---- gather codebook, STE output, loss partials ----
__global__ __launch_bounds__(256) void k_quant(const float* __restrict__ x,
                                               const float* __restrict__ w,
                                               float* __restrict__ out) {
    __shared__ double sr[256];
    double ls = 0.0;
    int stride = gridDim.x * 256;
    for (int e4 = blockIdx.x*256 + threadIdx.x; e4 < NROWS*DIM/4; e4 += stride) {
        int row = e4 >> 6, c4 = e4 & 63;
        int k = g_idx[row];
        float4 xv = ((const float4*)x)[e4];
        float4 qv = ((const float4*)w)[k*64 + c4];
        float d0 = __fsub_rn(qv.x, xv.x), d1 = __fsub_rn(qv.y, xv.y);
        float d2 = __fsub_rn(qv.z, xv.z), d3 = __fsub_rn(qv.w, xv.w);
        float* o = out + OFF_Q + (size_t)e4*4;
        o[0] = __fadd_rn(xv.x, d0); o[1] = __fadd_rn(xv.y, d1);
        o[2] = __fadd_rn(xv.z, d2); o[3] = __fadd_rn(xv.w, d3);
        float s4 = __fmaf_rn(d0, d0, __fmaf_rn(d1, d1, __fmaf_rn(d2, d2, d3*d3)));
        ls += (double)s4;
    }
    sr[threadIdx.x] = ls;
    __syncthreads();
    for (int o = 128; o; o >>= 1) { if (threadIdx.x < o) sr[threadIdx.x] += sr[threadIdx.x + o]; __syncthreads(); }
    if (!threadIdx.x) g_lp[blockIdx.x] = sr[0];
}

// ---- deterministic per-code counts + dw ----
__global__ __launch_bounds__(256) void k_counts(const float* __restrict__ x) {
    __shared__ int list[4096];
    __shared__ int cnt;
    int k = blockIdx.x, d = threadIdx.x;
    float acc = 0.f; int total = 0;
    for (int base = 0; base < NROWS; base += 4096) {
        if (!threadIdx.x) cnt = 0;
        __syncthreads();
        for (int i = threadIdx.x; i < 4096; i += 256)
            if (g_idx[base + i] == k) list[atomicAdd(&cnt, 1)] = base + i;
        __syncthreads();
        int m = cnt;
        for (int j = 0; j < m; j++) acc += x[(size_t)list[j]*DIM + d];
        total += m;
        __syncthreads();
    }
    g_dw[k*DIM + d] = acc;
    if (!threadIdx.x) g_counts[k] = (float)total;
}

// ---- scalars ----
__global__ __launch_bounds__(256) void k_scalars(const float* __restrict__ ecs,
                                                 float* __restrict__ out) {
    __shared__ double sd[256];
    int t = threadIdx.x;
    double s = 0;
    for (int i = t; i < 2048; i += 256) s += g_lp[i];
    sd[t] = s; __syncthreads();
    for (int o = 128; o; o >>= 1) { if (t < o) sd[t] += sd[t + o]; __syncthreads(); }
    double loss = 0.25 * sd[0] / ((double)NROWS * DIM);
    double ns = 0;
    for (int k = t; k < KCB; k += 256) {
        float ncs = __fadd_rn(__fmul_rn(0.99f, ecs[k]), __fmul_rn(0.01f, g_counts[k]));
        out[OFF_CS + k] = ncs;
        ns += ncs;
    }
    __syncthreads(); sd[t] = ns; __syncthreads();
    for (int o = 128; o; o >>= 1) { if (t < o) sd[t] += sd[t + o]; __syncthreads(); }
    float nf = (float)sd[0];
    float denom = __fadd_rn(nf, (float)(1024.0 * 1e-5));
    for (int k = t; k < KCB; k += 256) {
        float ncs = out[OFF_CS + k];
        g_cs[k] = __fmul_rn(__fdiv_rn(__fadd_rn(ncs, 1e-5f), denom), nf);
    }
    double ps = 0;
    for (int k = t; k < KCB; k += 256) {
        double p = (double)g_counts[k] / (double)NROWS;
        ps += p * log(p + 1e-10);
    }
    __syncthreads(); sd[t] = ps; __syncthreads();
    for (int o = 128; o; o >>= 1) { if (t < o) sd[t] += sd[t + o]; __syncthreads(); }
    if (!t) { out[OFF_LOSS] = (float)loss; out[OFF_PERP] = (float)exp(-sd[0]); }
}

// ---- EMA codebook update ----
__global__ __launch_bounds__(256) void k_emb(const float* __restrict__ emaw,
                                             float* __restrict__ out) {
    int e = blockIdx.x*256 + threadIdx.x;
    if (e >= KCB*DIM) return;
    int k = e >> 8;
    float ne = __fadd_rn(__fmul_rn(0.99f, emaw[e]), __fmul_rn(0.01f, g_dw[e]));
    out[OFF_EMA + e] = ne;
    out[OFF_EMB + e] = __fdiv_rn(ne, g_cs[k]);
}

extern "C" void kernel_launch(void* const* d_in, const int* in_sizes, int n_in,
                              void* d_out, int out_size) {
    const float* x    = (const float*)d_in[0];
    const float* w    = (const float*)d_in[1];
    const float* ecs  = (const float*)d_in[2];
    const float* emaw = (const float*)d_in[3];
    float* out = (float*)d_out;

    cudaFuncSetAttribute(k_mma_cand,
        cudaFuncAttributeMaxDynamicSharedMemorySize, SMEM_TOT);

    __nv_bfloat16 *xs0, *xs1, *ws0, *ws1;
    cudaGetSymbolAddress((void**)&xs0, g_xs0);
    cudaGetSymbolAddress((void**)&xs1, g_xs1);
    cudaGetSymbolAddress((void**)&ws0, g_ws0);
    cudaGetSymbolAddress((void**)&ws1, g_ws1);

    k_split<<<NROWS*DIM/4/256, 256>>>(x, NROWS*DIM/4, xs0, xs1);
    k_split<<<KCB*DIM/4/256,   256>>>(w, KCB*DIM/4,   ws0, ws1);
    k_rownorm<<<NROWS/8, 256>>>(x, NROWS, 0);
    k_rownorm<<<KCB/8,   256>>>(w, KCB,   1);
    k_mma_cand<<<NROWS/128, 256, SMEM_TOT>>>();
    k_rescore<<<NROWS/256, 256>>>(x, w);
    k_quant<<<2048, 256>>>(x, w, out);
    k_counts<<<KCB, 256>>>(x);
    k_scalars<<<1, 256>>>(ecs, out);
    k_emb<<<KCB*DIM/256, 256>>>(emaw, out);
}

// round 9
// speedup vs baseline: 1.9971x; 1.7098x over previous
#include <cuda_runtime.h>
#include <cuda_bf16.h>
#include <mma.h>
#include <math.h>

using namespace nvcuda;

#define NROWS 65536
#define DIM   256
#define KCB   1024

#define OFF_LOSS 0
#define OFF_Q    1
#define OFF_PERP (1 + NROWS*DIM)
#define OFF_EMB  (OFF_PERP + 1)
#define OFF_CS   (OFF_EMB + KCB*DIM)
#define OFF_EMA  (OFF_CS + KCB)

__device__ float  g_A[NROWS];
__device__ float  g_C[KCB];
__device__ int    g_idx[NROWS];
__device__ int    g_cand[NROWS*6];
__device__ float  g_counts[KCB];
__device__ float  g_dw[KCB*DIM];
__device__ float  g_cs[KCB];
__device__ double g_lp[2048];

__device__ __align__(16) __nv_bfloat16 g_xb[NROWS*DIM];
__device__ __align__(16) __nv_bfloat16 g_wb[KCB*DIM];

__device__ __forceinline__ unsigned smem_u32(const void* p) {
    unsigned a;
    asm("{ .reg .u64 t; cvta.to.shared.u64 t, %1; cvt.u32.u64 %0, t; }" : "=r"(a) : "l"(p));
    return a;
}
__device__ __forceinline__ int dless(float da, int ia, float db, int ib) {
    return (da < db) || (da == db && ia < ib);
}
#define CP_ASYNC16(dst, src) asm volatile("cp.async.cg.shared.global [%0], [%1], 16;" :: "r"(dst), "l"(src) : "memory")
#define CP_COMMIT()          asm volatile("cp.async.commit_group;" ::: "memory")
#define CP_WAIT(n)           asm volatile("cp.async.wait_group %0;" :: "n"(n) : "memory")

// ---------------- bf16 cast ----------------
__global__ __launch_bounds__(256) void k_cast(const float* __restrict__ s, int n4,
                                              __nv_bfloat16* __restrict__ d0) {
    int i = blockIdx.x * 256 + threadIdx.x;
    if (i >= n4) return;
    float4 v = ((const float4*)s)[i];
    ushort4 o0;
    o0.x = __bfloat16_as_ushort(__float2bfloat16_rn(v.x));
    o0.y = __bfloat16_as_ushort(__float2bfloat16_rn(v.y));
    o0.z = __bfloat16_as_ushort(__float2bfloat16_rn(v.z));
    o0.w = __bfloat16_as_ushort(__float2bfloat16_rn(v.w));
    ((ushort4*)d0)[i] = o0;
}

// ---- row squared norms (fp64-accumulated) ----
__global__ __launch_bounds__(256) void k_rownorm(const float* __restrict__ src,
                                                 int nrows, int which) {
    int wd = threadIdx.x >> 5, l = threadIdx.x & 31;
    int row = blockIdx.x * 8 + wd;
    if (row >= nrows) return;
    const float4* r4 = (const float4*)(src + (size_t)row * DIM);
    float4 a = r4[l], b = r4[l + 32];
    double s = (double)a.x*a.x + (double)a.y*a.y + (double)a.z*a.z + (double)a.w*a.w
             + (double)b.x*b.x + (double)b.y*b.y + (double)b.z*b.z + (double)b.w*b.w;
#pragma unroll
    for (int o = 16; o; o >>= 1) s += __shfl_down_sync(0xffffffffu, s, o);
    if (!l) { if (which) g_C[row] = (float)s; else g_A[row] = (float)s; }
}

// ---------------- wmma distance GEMM -> top-3 candidates per half ----------------
#define LDA 264
#define LDB 40
#define AS_BYTES (128*LDA*2)
#define BS_BYTES (128*LDB*2)
#define OFF_AS   0
#define OFF_BS   (AS_BYTES)
#define OFF_SC   (OFF_BS + 2*BS_BYTES)
#define OFF_SCR  (OFF_SC + 4096)
#define SMEM_TOT (OFF_SCR + 8192)

__device__ __forceinline__ void prefetch_b(char* smem, int tid, int buf, int kc, int ct) {
    int code = tid >> 1, half = tid & 1;
    const __nv_bfloat16* src = g_wb + (size_t)(ct + code) * DIM + kc * 32 + half * 16;
    unsigned dst = smem_u32(smem + OFF_BS + buf * BS_BYTES + (code * LDB + half * 16) * 2);
    CP_ASYNC16(dst, src);
    CP_ASYNC16(dst + 16, src + 8);
    CP_COMMIT();
}

__global__ __launch_bounds__(256,2) void k_mma_cand() {
    extern __shared__ char smem[];
    __nv_bfloat16* As = (__nv_bfloat16*)(smem + OFF_AS);
    float* sC = (float*)(smem + OFF_SC);
    int tid = threadIdx.x, w = tid >> 5, lane = tid & 31;
    int rowBase = blockIdx.x * 128;
    int rw = w >> 1, cw = w & 1;

    for (int i = tid; i < KCB; i += 256) sC[i] = g_C[i];

    // A resident: 128 rows x 256 K bf16
    for (int u = tid; u < 128 * 32; u += 256) {
        int r = u >> 5, c8 = u & 31;
        *(uint4*)(As + r * LDA + c8 * 8) =
            *(const uint4*)(g_xb + (size_t)(rowBase + r) * DIM + c8 * 8);
    }
    __syncthreads();

    int r_local = lane >> 1;
    int csub = (lane & 1) * 8;
    float Ar[2];
    Ar[0] = g_A[rowBase + rw * 32 + r_local];
    Ar[1] = g_A[rowBase + rw * 32 + 16 + r_local];
    float tD[2][3]; int tI[2][3];
#pragma unroll
    for (int fr = 0; fr < 2; fr++)
#pragma unroll
        for (int s = 0; s < 3; s++) { tD[fr][s] = 3.4e38f; tI[fr][s] = 0x7ffffff0 + s; }

    for (int ct8 = 0; ct8 < 8; ct8++) {
        int ct = ct8 * 128;
        wmma::fragment<wmma::accumulator, 16, 16, 16, float> acc[2][4];
#pragma unroll
        for (int fr = 0; fr < 2; fr++)
#pragma unroll
            for (int fc = 0; fc < 4; fc++) wmma::fill_fragment(acc[fr][fc], 0.0f);

        prefetch_b(smem, tid, 0, 0, ct);
        for (int kc = 0; kc < 8; kc++) {
            if (kc + 1 < 8) { prefetch_b(smem, tid, (kc + 1) & 1, kc + 1, ct); CP_WAIT(1); }
            else            { CP_WAIT(0); }
            __syncthreads();
            const __nv_bfloat16* Bs = (const __nv_bfloat16*)(smem + OFF_BS + (kc & 1) * BS_BYTES);
            int acol = kc * 32;
#pragma unroll
            for (int ks = 0; ks < 2; ks++) {
                wmma::fragment<wmma::matrix_a, 16, 16, 16, __nv_bfloat16, wmma::row_major> af[2];
                wmma::fragment<wmma::matrix_b, 16, 16, 16, __nv_bfloat16, wmma::col_major> bf[4];
#pragma unroll
                for (int fr = 0; fr < 2; fr++)
                    wmma::load_matrix_sync(af[fr], As + (rw * 32 + fr * 16) * LDA + acol + ks * 16, LDA);
#pragma unroll
                for (int fc = 0; fc < 4; fc++)
                    wmma::load_matrix_sync(bf[fc], Bs + (cw * 64 + fc * 16) * LDB + ks * 16, LDB);
#pragma unroll
                for (int fr = 0; fr < 2; fr++)
#pragma unroll
                    for (int fc = 0; fc < 4; fc++)
                        wmma::mma_sync(acc[fr][fc], af[fr], bf[fc], acc[fr][fc]);
            }
            __syncthreads();
        }

        // epilogue: approx distances -> per-thread top-3
        float* scr = (float*)(smem + OFF_SCR + w * 1024);
#pragma unroll
        for (int fr = 0; fr < 2; fr++)
#pragma unroll
            for (int fc = 0; fc < 4; fc++) {
                wmma::store_matrix_sync(scr, acc[fr][fc], 16, wmma::mem_row_major);
                __syncwarp();
                int cbase = ct + cw * 64 + fc * 16 + csub;
#pragma unroll
                for (int j = 0; j < 8; j++) {
                    float dot = scr[r_local * 16 + csub + j];
                    int code = cbase + j;
                    float d = __fadd_rn(__fsub_rn(Ar[fr], __fmul_rn(2.0f, dot)), sC[code]);
                    if (dless(d, code, tD[fr][0], tI[fr][0])) {
                        tD[fr][2] = tD[fr][1]; tI[fr][2] = tI[fr][1];
                        tD[fr][1] = tD[fr][0]; tI[fr][1] = tI[fr][0];
                        tD[fr][0] = d; tI[fr][0] = code;
                    } else if (dless(d, code, tD[fr][1], tI[fr][1])) {
                        tD[fr][2] = tD[fr][1]; tI[fr][2] = tI[fr][1];
                        tD[fr][1] = d; tI[fr][1] = code;
                    } else if (dless(d, code, tD[fr][2], tI[fr][2])) {
                        tD[fr][2] = d; tI[fr][2] = code;
                    }
                }
                __syncwarp();
            }
    }

    // merge lane pair (csub 0 & 8) -> top-3 per (row, half)
#pragma unroll
    for (int fr = 0; fr < 2; fr++) {
        float md[6]; int mi[6];
#pragma unroll
        for (int s = 0; s < 3; s++) {
            md[s] = tD[fr][s]; mi[s] = tI[fr][s];
            md[3 + s] = __shfl_xor_sync(0xffffffffu, tD[fr][s], 1);
            mi[3 + s] = __shfl_xor_sync(0xffffffffu, tI[fr][s], 1);
        }
#pragma unroll
        for (int p = 0; p < 3; p++)
#pragma unroll
            for (int q = p + 1; q < 6; q++)
                if (dless(md[q], mi[q], md[p], mi[p])) {
                    float td = md[p]; md[p] = md[q]; md[q] = td;
                    int   ti = mi[p]; mi[p] = mi[q]; mi[q] = ti;
                }
        if ((lane & 1) == 0) {
            int row = rowBase + rw * 32 + fr * 16 + r_local;
#pragma unroll
            for (int s = 0; s < 3; s++) g_cand[row * 6 + cw * 3 + s] = mi[s];
        }
    }
}

// ---------------- exact rescore (replicates R3 SIMT arithmetic) ----------------
__global__ __launch_bounds__(256) void k_rescore(const float* __restrict__ x,
                                                 const float* __restrict__ w) {
    int row = blockIdx.x * 256 + threadIdx.x;
    if (row >= NROWS) return;
    int c[6];
#pragma unroll
    for (int s = 0; s < 6; s++) c[s] = g_cand[row * 6 + s];
    const float4* xr = (const float4*)(x + (size_t)row * DIM);
    const float4* wr[6];
#pragma unroll
    for (int s = 0; s < 6; s++) wr[s] = (const float4*)(w + (size_t)c[s] * DIM);
    float dot[6] = {0.f, 0.f, 0.f, 0.f, 0.f, 0.f};
#pragma unroll 4
    for (int k4 = 0; k4 < 64; k4++) {
        float4 xv = xr[k4];
#pragma unroll
        for (int s = 0; s < 6; s++) {
            float4 wv = wr[s][k4];
            dot[s] = __fmaf_rn(xv.x, wv.x, dot[s]);
            dot[s] = __fmaf_rn(xv.y, wv.y, dot[s]);
            dot[s] = __fmaf_rn(xv.z, wv.z, dot[s]);
            dot[s] = __fmaf_rn(xv.w, wv.w, dot[s]);
        }
    }
    float A = g_A[row];
    float bd = 3.4e38f; int bi = 0x7fffffff;
#pragma unroll
    for (int s = 0; s < 6; s++) {
        float d = __fadd_rn(__fsub_rn(A, __fmul_rn(2.0f, dot[s])), g_C[c[s]]);
        if (dless(d, c[s], bd, bi)) { bd = d; bi = c[s]; }
    }
    g_idx[row] = bi;
}

// ---- gather codebook, STE output, loss partials ----
__global__ __launch_bounds__(256) void k_quant(const float* __restrict__ x,
                                               const float* __restrict__ w,
                                               float* __restrict__ out) {
    __shared__ double sr[256];
    double ls = 0.0;
    int stride = gridDim.x * 256;
    for (int e4 = blockIdx.x*256 + threadIdx.x; e4 < NROWS*DIM/4; e4 += stride) {
        int row = e4 >> 6, c4 = e4 & 63;
        int k = g_idx[row];
        float4 xv = ((const float4*)x)[e4];
        float4 qv = ((const float4*)w)[k*64 + c4];
        float d0 = __fsub_rn(qv.x, xv.x), d1 = __fsub_rn(qv.y, xv.y);
        float d2 = __fsub_rn(qv.z, xv.z), d3 = __fsub_rn(qv.w, xv.w);
        float* o = out + OFF_Q + (size_t)e4*4;
        o[0] = __fadd_rn(xv.x, d0); o[1] = __fadd_rn(xv.y, d1);
        o[2] = __fadd_rn(xv.z, d2); o[3] = __fadd_rn(xv.w, d3);
        float s4 = __fmaf_rn(d0, d0, __fmaf_rn(d1, d1, __fmaf_rn(d2, d2, d3*d3)));
        ls += (double)s4;
    }
    sr[threadIdx.x] = ls;
    __syncthreads();
    for (int o = 128; o; o >>= 1) { if (threadIdx.x < o) sr[threadIdx.x] += sr[threadIdx.x + o]; __syncthreads(); }
    if (!threadIdx.x) g_lp[blockIdx.x] = sr[0];
}

// ---- deterministic per-code counts + dw ----
__global__ __launch_bounds__(256) void k_counts(const float* __restrict__ x) {
    __shared__ int list[4096];
    __shared__ int cnt;
    int k = blockIdx.x, d = threadIdx.x;
    float acc = 0.f; int total = 0;
    for (int base = 0; base < NROWS; base += 4096) {
        if (!threadIdx.x) cnt = 0;
        __syncthreads();
        for (int i = threadIdx.x; i < 4096; i += 256)
            if (g_idx[base + i] == k) list[atomicAdd(&cnt, 1)] = base + i;
        __syncthreads();
        int m = cnt;
        for (int j = 0; j < m; j++) acc += x[(size_t)list[j]*DIM + d];
        total += m;
        __syncthreads();
    }
    g_dw[k*DIM + d] = acc;
    if (!threadIdx.x) g_counts[k] = (float)total;
}

// ---- scalars ----
__global__ __launch_bounds__(256) void k_scalars(const float* __restrict__ ecs,
                                                 float* __restrict__ out) {
    __shared__ double sd[256];
    int t = threadIdx.x;
    double s = 0;
    for (int i = t; i < 2048; i += 256) s += g_lp[i];
    sd[t] = s; __syncthreads();
    for (int o = 128; o; o >>= 1) { if (t < o) sd[t] += sd[t + o]; __syncthreads(); }
    double loss = 0.25 * sd[0] / ((double)NROWS * DIM);
    double ns = 0;
    for (int k = t; k < KCB; k += 256) {
        float ncs = __fadd_rn(__fmul_rn(0.99f, ecs[k]), __fmul_rn(0.01f, g_counts[k]));
        out[OFF_CS + k] = ncs;
        ns += ncs;
    }
    __syncthreads(); sd[t] = ns; __syncthreads();
    for (int o = 128; o; o >>= 1) { if (t < o) sd[t] += sd[t + o]; __syncthreads(); }
    float nf = (float)sd[0];
    float denom = __fadd_rn(nf, (float)(1024.0 * 1e-5));
    for (int k = t; k < KCB; k += 256) {
        float ncs = out[OFF_CS + k];
        g_cs[k] = __fmul_rn(__fdiv_rn(__fadd_rn(ncs, 1e-5f), denom), nf);
    }
    double ps = 0;
    for (int k = t; k < KCB; k += 256) {
        double p = (double)g_counts[k] / (double)NROWS;
        ps += p * log(p + 1e-10);
    }
    __syncthreads(); sd[t] = ps; __syncthreads();
    for (int o = 128; o; o >>= 1) { if (t < o) sd[t] += sd[t + o]; __syncthreads(); }
    if (!t) { out[OFF_LOSS] = (float)loss; out[OFF_PERP] = (float)exp(-sd[0]); }
}

// ---- EMA codebook update ----
__global__ __launch_bounds__(256) void k_emb(const float* __restrict__ emaw,
                                             float* __restrict__ out) {
    int e = blockIdx.x*256 + threadIdx.x;
    if (e >= KCB*DIM) return;
    int k = e >> 8;
    float ne = __fadd_rn(__fmul_rn(0.99f, emaw[e]), __fmul_rn(0.01f, g_dw[e]));
    out[OFF_EMA + e] = ne;
    out[OFF_EMB + e] = __fdiv_rn(ne, g_cs[k]);
}

extern "C" void kernel_launch(void* const* d_in, const int* in_sizes, int n_in,
                              void* d_out, int out_size) {
    const float* x    = (const float*)d_in[0];
    const float* w    = (const float*)d_in[1];
    const float* ecs  = (const float*)d_in[2];
    const float* emaw = (const float*)d_in[3];
    float* out = (float*)d_out;

    cudaFuncSetAttribute(k_mma_cand,
        cudaFuncAttributeMaxDynamicSharedMemorySize, SMEM_TOT);

    __nv_bfloat16 *xb, *wb;
    cudaGetSymbolAddress((void**)&xb, g_xb);
    cudaGetSymbolAddress((void**)&wb, g_wb);

    k_cast<<<NROWS*DIM/4/256, 256>>>(x, NROWS*DIM/4, xb);
    k_cast<<<KCB*DIM/4/256,   256>>>(w, KCB*DIM/4,   wb);
    k_rownorm<<<NROWS/8, 256>>>(x, NROWS, 0);
    k_rownorm<<<KCB/8,   256>>>(w, KCB,   1);
    k_mma_cand<<<NROWS/128, 256, SMEM_TOT>>>();
    k_rescore<<<NROWS/256, 256>>>(x, w);
    k_quant<<<2048, 256>>>(x, w, out);
    k_counts<<<KCB, 256>>>(x);
    k_scalars<<<1, 256>>>(ecs, out);
    k_emb<<<KCB*DIM/256, 256>>>(emaw, out);
}